// round 9
// baseline (speedup 1.0000x reference)
#include <cuda_runtime.h>
#include <cuda_fp16.h>
#include <cstdint>

#define B_    8
#define HW_   32
#define C_    32
#define F_    64
#define FQ_   16
#define HO_   30
#define WO_   30
#define K_    288
#define KPADH 296   // halfs per w_sm row: 592B stride -> fl*148 mod 32 distinct per 8-lane phase

// device scratch: transposed half w [f][k]
__device__ __align__(16) __half g_wT[F_ * K_];

__device__ __forceinline__ unsigned h2u(__half2 h)
{
    unsigned u; memcpy(&u, &h, 4); return u;
}
__device__ __forceinline__ __half2 f_as_h2(float f)
{
    __half2 h; unsigned u = __float_as_uint(f); memcpy(&h, &u, 4); return h;
}

// ---- tiny pre-pass: w fp32 [k][64] -> half transposed [f][288] ----
__global__ void convert_w(const float* __restrict__ w)
{
    int j = blockIdx.x * 512 + threadIdx.x;
    #pragma unroll
    for (int r = 0; r < 2; ++r, j += 256) {
        if (j < F_ * K_) {
            int f = j / K_, k = j - f * K_;
            g_wT[j] = __float2half_rn(w[k * F_ + f]);
        }
    }
}

#define ACCH(mx, mn, pf, wf)                                                    \
    do {                                                                        \
        __half2 s_;                                                             \
        s_ = __hadd2(f_as_h2(pf.x), f_as_h2(wf.x)); mx = __hmax2(mx, s_); mn = __hmin2(mn, s_); \
        s_ = __hadd2(f_as_h2(pf.y), f_as_h2(wf.y)); mx = __hmax2(mx, s_); mn = __hmin2(mn, s_); \
        s_ = __hadd2(f_as_h2(pf.z), f_as_h2(wf.z)); mx = __hmax2(mx, s_); mn = __hmin2(mn, s_); \
        s_ = __hadd2(f_as_h2(pf.w), f_as_h2(wf.w)); mx = __hmax2(mx, s_); mn = __hmin2(mn, s_); \
    } while (0)

__global__ __launch_bounds__(128, 10)
void tropconv_h2(const float* __restrict__ x,
                 const float* __restrict__ bias,
                 float* __restrict__ out)
{
    __shared__ __align__(16) __half w_sm[FQ_ * KPADH];   // [16][296]  9472B
    __shared__ __align__(16) __half x_sm[3 * HW_ * C_];  // [3][32][32] 6144B

    const int tid = threadIdx.x;
    const int fq  = blockIdx.x & 3;           // filter quarter
    const int h   = (blockIdx.x >> 2) & 1;    // wo half: 0 -> wo 0..15, 1 -> wo 14..29
    const int row = blockIdx.x >> 3;          // b*30 + ho
    const int ho  = row % HO_;
    const int b   = row / HO_;

    // ---- w slice from g_wT: 576 vec8 (16B) chunks, repacked to padded rows ----
    {
        const char* src = (const char*)(g_wT + fq * FQ_ * K_);
        char* dst = (char*)w_sm;
        #pragma unroll
        for (int idx = tid; idx < 576; idx += 128) {
            int fl = idx / 36;                // 36 chunks per 288-half row
            int k8 = idx - fl * 36;
            *(float4*)(dst + fl * (KPADH * 2) + k8 * 16) =
                *(const float4*)(src + fl * (K_ * 2) + k8 * 16);
        }
    }
    // ---- x slab: 3 rows fp32 -> half inline (768 float4) ----
    {
        const float4* src = (const float4*)(x + (b * HW_ + ho) * (HW_ * C_));
        uint2* dst = (uint2*)x_sm;
        #pragma unroll
        for (int idx = tid; idx < 768; idx += 128) {
            float4 v = src[idx];
            dst[idx] = make_uint2(h2u(__floats2half2_rn(v.x, v.y)),
                                  h2u(__floats2half2_rn(v.z, v.w)));
        }
    }
    __syncthreads();

    const int fl   = tid & 15;                // local filter 0..15
    const int slot = tid >> 4;                // 0..7
    const int wo_base = h * 14 + slot * 2;    // max 28; cols needed <= wo_base+3 = 31

    const char* wrowb = (const char*)w_sm + fl * (KPADH * 2);   // 592B stride, 16B aligned
    const char* xb = (const char*)x_sm;
    const float bv = __ldg(bias + fq * FQ_ + fl);

    const __half2 HNEG = __float2half2_rn(-65504.0f);
    const __half2 HPOS = __float2half2_rn(65504.0f);
    __half2 mx2[2], mn2[2];
    #pragma unroll
    for (int t = 0; t < 2; ++t) { mx2[t] = HNEG; mn2[t] = HPOS; }

    #pragma unroll 1
    for (int c4 = 0; c4 < 4; ++c4) {          // 4 chunks of 8 channels
        #pragma unroll
        for (int i = 0; i < 3; ++i) {
            float4 pv[4];                     // cols wo_base .. wo_base+3
            #pragma unroll
            for (int u = 0; u < 4; ++u)
                pv[u] = *(const float4*)(xb + i * 2048 + (wo_base + u) * 64 + c4 * 16);

            #pragma unroll
            for (int j = 0; j < 3; ++j) {
                float4 wv = *(const float4*)(wrowb + (i * 3 + j) * 64 + c4 * 16);
                ACCH(mx2[0], mn2[0], pv[j],     wv);
                ACCH(mx2[1], mn2[1], pv[j + 1], wv);
            }
        }
    }

    #pragma unroll
    for (int t = 0; t < 2; ++t) {
        int wo = wo_base + t;                 // always < 30 by construction
        float hx = fmaxf(__low2float(mx2[t]), __high2float(mx2[t]));
        float hn = fminf(__low2float(mn2[t]), __high2float(mn2[t]));
        out[(row * WO_ + wo) * F_ + fq * FQ_ + fl] = hx - hn + bv;
    }
}

extern "C" void kernel_launch(void* const* d_in, const int* in_sizes, int n_in,
                              void* d_out, int out_size)
{
    const float* x    = (const float*)d_in[0];
    const float* w    = (const float*)d_in[1];
    const float* bias = (const float*)d_in[2];
    float* out        = (float*)d_out;

    convert_w<<<36, 256>>>(w);
    tropconv_h2<<<B_ * HO_ * 8, 128>>>(x, bias, out);
}

// round 10
// speedup vs baseline: 1.1404x; 1.1404x over previous
#include <cuda_runtime.h>
#include <cuda_fp16.h>
#include <cstdint>

#define B_    8
#define HW_   32
#define C_    32
#define F_    64
#define FQ_   16
#define HO_   30
#define WO_   30
#define K_    288
#define KPADH 296   // halfs per w_sm row: 592B stride -> fl*148 mod 32 distinct per 8-lane phase

__device__ __forceinline__ unsigned h2u(__half2 h)
{
    unsigned u; memcpy(&u, &h, 4); return u;
}
__device__ __forceinline__ __half2 f_as_h2(float f)
{
    __half2 h; unsigned u = __float_as_uint(f); memcpy(&h, &u, 4); return h;
}

#define ACCH(mx, mn, pf, wf)                                                    \
    do {                                                                        \
        __half2 s_;                                                             \
        s_ = __hadd2(f_as_h2(pf.x), f_as_h2(wf.x)); mx = __hmax2(mx, s_); mn = __hmin2(mn, s_); \
        s_ = __hadd2(f_as_h2(pf.y), f_as_h2(wf.y)); mx = __hmax2(mx, s_); mn = __hmin2(mn, s_); \
        s_ = __hadd2(f_as_h2(pf.z), f_as_h2(wf.z)); mx = __hmax2(mx, s_); mn = __hmin2(mn, s_); \
        s_ = __hadd2(f_as_h2(pf.w), f_as_h2(wf.w)); mx = __hmax2(mx, s_); mn = __hmin2(mn, s_); \
    } while (0)

__global__ __launch_bounds__(128, 8)
void tropconv_h2(const float* __restrict__ x,
                 const float* __restrict__ w,
                 const float* __restrict__ bias,
                 float* __restrict__ out)
{
    __shared__ __align__(16) __half w_sm[FQ_ * KPADH];   // [16][296]  9472B
    __shared__ __align__(16) __half x_sm[3 * HW_ * C_];  // [3][32][32] 6144B

    const int tid = threadIdx.x;
    const int fq  = blockIdx.x & 3;           // filter quarter
    const int row = blockIdx.x >> 2;          // b*30 + ho
    const int ho  = row % HO_;
    const int b   = row / HO_;

    // ---- inline w transpose+convert: global w [k][64] fp32 -> w_sm [16][296] half ----
    // 1152 float4 chunks (4 f-values at one k): 9 per thread
    #pragma unroll
    for (int idx = tid; idx < K_ * 4; idx += 128) {
        int k  = idx >> 2;
        int f4 = idx & 3;
        float4 v = *(const float4*)(w + k * F_ + fq * FQ_ + f4 * 4);
        __half* dst = w_sm + (f4 * 4) * KPADH + k;
        dst[0 * KPADH] = __float2half_rn(v.x);
        dst[1 * KPADH] = __float2half_rn(v.y);
        dst[2 * KPADH] = __float2half_rn(v.z);
        dst[3 * KPADH] = __float2half_rn(v.w);
    }
    // ---- inline x convert: 3 rows fp32 -> half (768 float4, 6 per thread) ----
    {
        const float4* src = (const float4*)(x + (b * HW_ + ho) * (HW_ * C_));
        uint2* dst = (uint2*)x_sm;
        #pragma unroll
        for (int idx = tid; idx < 768; idx += 128) {
            float4 v = src[idx];
            dst[idx] = make_uint2(h2u(__floats2half2_rn(v.x, v.y)),
                                  h2u(__floats2half2_rn(v.z, v.w)));
        }
    }
    __syncthreads();

    const int fl   = tid & 15;                // local filter 0..15
    const int slot = tid >> 4;                // wo-group 0..7
    const int wo_base = slot * 4;

    const char* wrowb = (const char*)w_sm + fl * (KPADH * 2);   // 592B stride, 16B aligned
    const char* xb = (const char*)x_sm;
    const float bv = __ldg(bias + fq * FQ_ + fl);

    // clamped column byte-offsets
    int coff[6];
    #pragma unroll
    for (int u = 0; u < 6; ++u) {
        int col = wo_base + u;
        if (col > 31) col = 31;               // garbage only feeds masked stores
        coff[u] = col * 64;
    }

    const __half2 HNEG = __float2half2_rn(-65504.0f);
    const __half2 HPOS = __float2half2_rn(65504.0f);
    __half2 mx2[4], mn2[4];
    #pragma unroll
    for (int t = 0; t < 4; ++t) { mx2[t] = HNEG; mn2[t] = HPOS; }

    #pragma unroll 1
    for (int c4 = 0; c4 < 4; ++c4) {          // 4 chunks of 8 channels
        #pragma unroll
        for (int i = 0; i < 3; ++i) {
            float4 pv[6];                     // broadcast LDS.128 per 8-lane phase
            #pragma unroll
            for (int u = 0; u < 6; ++u)
                pv[u] = *(const float4*)(xb + i * 2048 + coff[u] + c4 * 16);

            #pragma unroll
            for (int j = 0; j < 3; ++j) {
                float4 wv = *(const float4*)(wrowb + (i * 3 + j) * 64 + c4 * 16);
                #pragma unroll
                for (int t = 0; t < 4; ++t)
                    ACCH(mx2[t], mn2[t], pv[j + t], wv);
            }
        }
    }

    #pragma unroll
    for (int t = 0; t < 4; ++t) {
        int wo = wo_base + t;
        if (wo < WO_) {
            float hx = fmaxf(__low2float(mx2[t]), __high2float(mx2[t]));
            float hn = fminf(__low2float(mn2[t]), __high2float(mn2[t]));
            out[(row * WO_ + wo) * F_ + fq * FQ_ + fl] = hx - hn + bv;
        }
    }
}

extern "C" void kernel_launch(void* const* d_in, const int* in_sizes, int n_in,
                              void* d_out, int out_size)
{
    const float* x    = (const float*)d_in[0];
    const float* w    = (const float*)d_in[1];
    const float* bias = (const float*)d_in[2];
    float* out        = (float*)d_out;

    tropconv_h2<<<B_ * HO_ * 4, 128>>>(x, w, bias, out);
}